// round 3
// baseline (speedup 1.0000x reference)
#include <cuda_runtime.h>
#include <cuda_bf16.h>
#include <mma.h>
#include <math.h>

using namespace nvcuda;

// Problem dims
#define Ss  256
#define Bb  64
#define Ii  1024
#define Hh  1024
#define H3  3072
#define Pp  1024
#define Ll  256

typedef __nv_bfloat16 bf16;

// ---------------- scratch (static device allocations) ----------------
__device__ float g_GI[(size_t)Ss * Bb * H3];       // input gates (no bias)
__device__ float g_Q [(size_t)Ss * Bb * Pp];       // queries (no bias)
__device__ float g_h [Bb * Hh];                    // running hidden fp32

__device__ bf16 g_inch[(size_t)Ss * Bb * Ii];      // incoming split hi
__device__ bf16 g_incl[(size_t)Ss * Bb * Ii];      // incoming split lo
__device__ bf16 g_Wih_h[(size_t)H3 * Ii], g_Wih_l[(size_t)H3 * Ii];
__device__ bf16 g_Whh_h[(size_t)H3 * Hh], g_Whh_l[(size_t)H3 * Hh];
__device__ bf16 g_Wq_h [(size_t)Pp * Hh], g_Wq_l [(size_t)Pp * Hh];
__device__ bf16 g_ch_h[2][Bb * Hh];                // current-h split ping-pong
__device__ bf16 g_ch_l[2][Bb * Hh];
__device__ bf16 g_hsh[(size_t)Ss * Bb * Hh];       // h history split hi
__device__ bf16 g_hsl[(size_t)Ss * Bb * Hh];       // h history split lo

// ---------------- split fp32 -> (hi, lo) bf16 ----------------
__global__ void split_kernel(const float* __restrict__ x,
                             bf16* __restrict__ hi, bf16* __restrict__ lo, int n)
{
    int i = blockIdx.x * blockDim.x + threadIdx.x;
    if (i < n) {
        float v = x[i];
        bf16 h = __float2bfloat16(v);
        hi[i] = h;
        lo[i] = __float2bfloat16(v - __bfloat162float(h));
    }
}

// ---------------- split-bf16 NT GEMM via wmma: C = A * B^T ----------------
// A: [M,K] row-major (splits Ah/Al), B: [N,K] row-major (splits Bh/Bl).
// Block tile 128x128, BK=16, 256 threads = 8 warps (2x4), warp tile 64x32.
#define WBM 128
#define WBN 128
#define WBK 16

__global__ void __launch_bounds__(256)
wmma_nt_split(const bf16* __restrict__ Ah, const bf16* __restrict__ Al, int lda,
              const bf16* __restrict__ Bh, const bf16* __restrict__ Bl, int ldb,
              float* __restrict__ C, int ldc, int K)
{
    __shared__ __align__(16) bf16 sAh[WBM][WBK], sAl[WBM][WBK];
    __shared__ __align__(16) bf16 sBh[WBN][WBK], sBl[WBN][WBK];

    int m0 = blockIdx.x * WBM, n0 = blockIdx.y * WBN;
    int tid = threadIdx.x;
    int w = tid >> 5;
    int wr = w >> 2, wc = w & 3;        // warp grid 2x4

    wmma::fragment<wmma::accumulator,16,16,16,float> acc[4][2];
#pragma unroll
    for (int i = 0; i < 4; i++)
#pragma unroll
        for (int j = 0; j < 2; j++) wmma::fill_fragment(acc[i][j], 0.f);

    int r = tid >> 1, hf = tid & 1;     // 128 rows x 2 halves (8 bf16 each)

    for (int k0 = 0; k0 < K; k0 += WBK) {
        *reinterpret_cast<uint4*>(&sAh[r][hf*8]) =
            *reinterpret_cast<const uint4*>(Ah + (size_t)(m0 + r) * lda + k0 + hf*8);
        *reinterpret_cast<uint4*>(&sAl[r][hf*8]) =
            *reinterpret_cast<const uint4*>(Al + (size_t)(m0 + r) * lda + k0 + hf*8);
        *reinterpret_cast<uint4*>(&sBh[r][hf*8]) =
            *reinterpret_cast<const uint4*>(Bh + (size_t)(n0 + r) * ldb + k0 + hf*8);
        *reinterpret_cast<uint4*>(&sBl[r][hf*8]) =
            *reinterpret_cast<const uint4*>(Bl + (size_t)(n0 + r) * ldb + k0 + hf*8);
        __syncthreads();

        wmma::fragment<wmma::matrix_a,16,16,16,bf16,wmma::row_major> ah[4], al[4];
        wmma::fragment<wmma::matrix_b,16,16,16,bf16,wmma::col_major> bh[2], bl[2];
#pragma unroll
        for (int i = 0; i < 4; i++) {
            wmma::load_matrix_sync(ah[i], &sAh[wr*64 + i*16][0], WBK);
            wmma::load_matrix_sync(al[i], &sAl[wr*64 + i*16][0], WBK);
        }
#pragma unroll
        for (int j = 0; j < 2; j++) {
            wmma::load_matrix_sync(bh[j], &sBh[wc*32 + j*16][0], WBK);
            wmma::load_matrix_sync(bl[j], &sBl[wc*32 + j*16][0], WBK);
        }
#pragma unroll
        for (int i = 0; i < 4; i++)
#pragma unroll
            for (int j = 0; j < 2; j++) {
                wmma::mma_sync(acc[i][j], ah[i], bh[j], acc[i][j]);
                wmma::mma_sync(acc[i][j], ah[i], bl[j], acc[i][j]);
                wmma::mma_sync(acc[i][j], al[i], bh[j], acc[i][j]);
            }
        __syncthreads();
    }
#pragma unroll
    for (int i = 0; i < 4; i++)
#pragma unroll
        for (int j = 0; j < 2; j++)
            wmma::store_matrix_sync(
                C + (size_t)(m0 + wr*64 + i*16) * ldc + n0 + wc*32 + j*16,
                acc[i][j], ldc, wmma::mem_row_major);
}

// ---------------- fused scan step: gh MMA + GRU nonlinearity ----------------
// grid = 128 blocks (8 hidden units each), 128 threads (4 warps).
// Block computes gh[64 b][24 gate-cols] (padded to 32) with K=1024, BK=64.
__global__ void __launch_bounds__(128)
gru_scan_step(int t,
              const bf16* __restrict__ hinH, const bf16* __restrict__ hinL,
              bf16* __restrict__ houtH, bf16* __restrict__ houtL,
              const float* __restrict__ bih, const float* __restrict__ bhh,
              const int* __restrict__ length, float* __restrict__ hs)
{
    __shared__ __align__(16) bf16 sAh[64][64], sAl[64][64];
    __shared__ __align__(16) bf16 sBh[32][64], sBl[32][64];
    __shared__ float ghsm[64][32];

    int js = blockIdx.x * 8;
    int tid = threadIdx.x, w = tid >> 5;

    wmma::fragment<wmma::accumulator,16,16,16,float> acc[2];
    wmma::fill_fragment(acc[0], 0.f);
    wmma::fill_fragment(acc[1], 0.f);

    for (int k0 = 0; k0 < Hh; k0 += 64) {
        // A tiles: h split, 64 rows x 64 cols (8 uint4 per row)
#pragma unroll
        for (int s = tid; s < 512; s += 128) {
            int rr = s >> 3, cc = (s & 7) * 8;
            *reinterpret_cast<uint4*>(&sAh[rr][cc]) =
                *reinterpret_cast<const uint4*>(hinH + rr*Hh + k0 + cc);
            *reinterpret_cast<uint4*>(&sAl[rr][cc]) =
                *reinterpret_cast<const uint4*>(hinL + rr*Hh + k0 + cc);
        }
        // B tiles: W_hh rows {g*1024 + js + u : g=0..2, u=0..7}, rows 24..31 zero
#pragma unroll
        for (int s = tid; s < 256; s += 128) {
            int rb = s >> 3, cc = (s & 7) * 8;
            if (rb < 24) {
                size_t wrow = (size_t)((rb >> 3) * 1024 + js + (rb & 7));
                *reinterpret_cast<uint4*>(&sBh[rb][cc]) =
                    *reinterpret_cast<const uint4*>(g_Whh_h + wrow*Hh + k0 + cc);
                *reinterpret_cast<uint4*>(&sBl[rb][cc]) =
                    *reinterpret_cast<const uint4*>(g_Whh_l + wrow*Hh + k0 + cc);
            } else {
                uint4 z = make_uint4(0,0,0,0);
                *reinterpret_cast<uint4*>(&sBh[rb][cc]) = z;
                *reinterpret_cast<uint4*>(&sBl[rb][cc]) = z;
            }
        }
        __syncthreads();
#pragma unroll
        for (int kk = 0; kk < 4; kk++) {
            wmma::fragment<wmma::matrix_a,16,16,16,bf16,wmma::row_major> ah, al;
            wmma::fragment<wmma::matrix_b,16,16,16,bf16,wmma::col_major> bh[2], bl[2];
            wmma::load_matrix_sync(ah, &sAh[w*16][kk*16], 64);
            wmma::load_matrix_sync(al, &sAl[w*16][kk*16], 64);
            wmma::load_matrix_sync(bh[0], &sBh[0][kk*16], 64);
            wmma::load_matrix_sync(bl[0], &sBl[0][kk*16], 64);
            wmma::load_matrix_sync(bh[1], &sBh[16][kk*16], 64);
            wmma::load_matrix_sync(bl[1], &sBl[16][kk*16], 64);
#pragma unroll
            for (int j = 0; j < 2; j++) {
                wmma::mma_sync(acc[j], ah, bh[j], acc[j]);
                wmma::mma_sync(acc[j], ah, bl[j], acc[j]);
                wmma::mma_sync(acc[j], al, bh[j], acc[j]);
            }
        }
        __syncthreads();
    }
    wmma::store_matrix_sync(&ghsm[w*16][0],  acc[0], 32, wmma::mem_row_major);
    wmma::store_matrix_sync(&ghsm[w*16][16], acc[1], 32, wmma::mem_row_major);
    __syncthreads();

    // GRU nonlinearity for 8 units x 64 batches
#pragma unroll
    for (int e = tid; e < 512; e += 128) {
        int b = e >> 3, u = e & 7;
        int j = js + u;
        size_t gib = ((size_t)t * Bb + b) * H3;
        float ghr = ghsm[b][u]      + bhh[j];
        float ghz = ghsm[b][8 + u]  + bhh[Hh + j];
        float ghn = ghsm[b][16 + u] + bhh[2*Hh + j];
        float gir = g_GI[gib + j]          + bih[j];
        float giz = g_GI[gib + Hh + j]     + bih[Hh + j];
        float gin = g_GI[gib + 2*Hh + j]   + bih[2*Hh + j];
        float h = g_h[b*Hh + j];
        float rg = 1.f / (1.f + expf(-(gir + ghr)));
        float zg = 1.f / (1.f + expf(-(giz + ghz)));
        float ng = tanhf(gin + rg * ghn);
        float keep = (t < length[b]) ? 1.f : 0.f;
        float hn = (ng + zg * (h - ng)) * keep;

        g_h[b*Hh + j] = hn;
        bf16 hhi = __float2bfloat16(hn);
        bf16 hlo = __float2bfloat16(hn - __bfloat162float(hhi));
        houtH[b*Hh + j] = hhi;
        houtL[b*Hh + j] = hlo;
        size_t hidx = ((size_t)t * Bb + b) * Hh + j;
        g_hsh[hidx] = hhi;
        g_hsl[hidx] = hlo;
        hs[((size_t)t * Bb + b) * 2048 + j] = hn;
    }
}

// ---------------- fp32 NT GEMM (kept for scores) ----------------
template<int BM,int BN,int BK,int TM,int TN>
__global__ void __launch_bounds__((BM/TM)*(BN/TN))
gemm_nt(const float* __restrict__ A, int lda, int batchA,
        const float* __restrict__ B, int ldb, int batchB,
        float* __restrict__ C, int ldc, int cstride, int batchC,
        const float* __restrict__ bias,
        int M, int N, int K, int kChunk)
{
    constexpr int TH = (BM/TM)*(BN/TN);
    __shared__ float As[BK][BM];
    __shared__ float Bs[BK][BN];

    int z = blockIdx.z;
    A += (size_t)z * batchA;
    B += (size_t)z * batchB;
    C += (size_t)z * batchC;
    int kbeg = 0, kend = K;
    if (kChunk) { kbeg = z * kChunk; kend = kbeg + kChunk; }

    int m0 = blockIdx.x * BM, n0 = blockIdx.y * BN;
    int tid = threadIdx.x;
    int tx = tid % (BN/TN), ty = tid / (BN/TN);

    float acc[TM][TN];
#pragma unroll
    for (int i = 0; i < TM; i++)
#pragma unroll
        for (int j = 0; j < TN; j++) acc[i][j] = 0.f;

    for (int k0 = kbeg; k0 < kend; k0 += BK) {
        {
            constexpr int V = BM * BK / 4;
#pragma unroll
            for (int v = tid; v < V; v += TH) {
                int k4 = v % (BK/4);
                int m  = v / (BK/4);
                float4 a = *reinterpret_cast<const float4*>(
                    A + (size_t)(m0 + m) * lda + k0 + k4 * 4);
                As[k4*4+0][m] = a.x; As[k4*4+1][m] = a.y;
                As[k4*4+2][m] = a.z; As[k4*4+3][m] = a.w;
            }
        }
        {
            constexpr int V = BN * BK / 4;
#pragma unroll
            for (int v = tid; v < V; v += TH) {
                int k4 = v % (BK/4);
                int n  = v / (BK/4);
                float4 b = *reinterpret_cast<const float4*>(
                    B + (size_t)(n0 + n) * ldb + k0 + k4 * 4);
                Bs[k4*4+0][n] = b.x; Bs[k4*4+1][n] = b.y;
                Bs[k4*4+2][n] = b.z; Bs[k4*4+3][n] = b.w;
            }
        }
        __syncthreads();
#pragma unroll
        for (int k = 0; k < BK; k++) {
            float fa[TM], fb[TN];
#pragma unroll
            for (int i = 0; i < TM; i++) fa[i] = As[k][ty*TM + i];
#pragma unroll
            for (int j = 0; j < TN; j++) fb[j] = Bs[k][tx*TN + j];
#pragma unroll
            for (int i = 0; i < TM; i++)
#pragma unroll
                for (int j = 0; j < TN; j++)
                    acc[i][j] += fa[i] * fb[j];
        }
        __syncthreads();
    }

#pragma unroll
    for (int i = 0; i < TM; i++) {
        int m = m0 + ty*TM + i;
#pragma unroll
        for (int j = 0; j < TN; j++) {
            int n = n0 + tx*TN + j;
            float v = acc[i][j];
            if (bias) v += bias[n];
            C[(size_t)m * ldc + (size_t)n * cstride] = v;
        }
    }
}

// ---------------- fp32 NN GEMM (kept for context) ----------------
template<int BM,int BN,int BK,int TM,int TN>
__global__ void __launch_bounds__((BM/TM)*(BN/TN))
gemm_nn(const float* __restrict__ A, int ldaR, int ldaE, int batchA,
        const float* __restrict__ B, int ldb, int batchB,
        float* __restrict__ C, int ldc, int batchC,
        int M, int N, int K)
{
    constexpr int TH = (BM/TM)*(BN/TN);
    __shared__ float As[BK][BM];
    __shared__ float Bs[BK][BN];

    int z = blockIdx.z;
    A += (size_t)z * batchA;
    B += (size_t)z * batchB;
    C += (size_t)z * batchC;

    int m0 = blockIdx.x * BM, n0 = blockIdx.y * BN;
    int tid = threadIdx.x;
    int tx = tid % (BN/TN), ty = tid / (BN/TN);

    float acc[TM][TN];
#pragma unroll
    for (int i = 0; i < TM; i++)
#pragma unroll
        for (int j = 0; j < TN; j++) acc[i][j] = 0.f;

    for (int k0 = 0; k0 < K; k0 += BK) {
#pragma unroll
        for (int e = tid; e < BM*BK; e += TH) {
            int m = e / BK, k = e % BK;
            As[k][m] = A[(size_t)(m0 + m) * ldaR + (size_t)(k0 + k) * ldaE];
        }
        {
            constexpr int V = BN * BK / 4;
#pragma unroll
            for (int v = tid; v < V; v += TH) {
                int n4 = v % (BN/4);
                int k  = v / (BN/4);
                float4 b = *reinterpret_cast<const float4*>(
                    B + (size_t)(k0 + k) * ldb + n0 + n4 * 4);
                Bs[k][n4*4+0] = b.x; Bs[k][n4*4+1] = b.y;
                Bs[k][n4*4+2] = b.z; Bs[k][n4*4+3] = b.w;
            }
        }
        __syncthreads();
#pragma unroll
        for (int k = 0; k < BK; k++) {
            float fa[TM], fb[TN];
#pragma unroll
            for (int i = 0; i < TM; i++) fa[i] = As[k][ty*TM + i];
#pragma unroll
            for (int j = 0; j < TN; j++) fb[j] = Bs[k][tx*TN + j];
#pragma unroll
            for (int i = 0; i < TM; i++)
#pragma unroll
                for (int j = 0; j < TN; j++)
                    acc[i][j] += fa[i] * fb[j];
        }
        __syncthreads();
    }

#pragma unroll
    for (int i = 0; i < TM; i++) {
        int m = m0 + ty*TM + i;
#pragma unroll
        for (int j = 0; j < TN; j++) {
            int n = n0 + tx*TN + j;
            C[(size_t)m * ldc + n] = acc[i][j];
        }
    }
}

// ---------------- small kernels ----------------
__global__ void init_h_kernel(const float* __restrict__ h_init) {
    int idx = blockIdx.x * blockDim.x + threadIdx.x;   // 65536
    float v = h_init[idx & (Hh - 1)];
    g_h[idx] = v;
    bf16 hi = __float2bfloat16(v);
    g_ch_h[0][idx] = hi;
    g_ch_l[0][idx] = __float2bfloat16(v - __bfloat162float(hi));
}

__global__ void biasq_kernel(const float* __restrict__ bq) {
    int idx = blockIdx.x * blockDim.x + threadIdx.x;
    g_Q[idx] += bq[idx & (Pp - 1)];
}

__global__ void softmax_kernel(float* __restrict__ attn,
                               const int* __restrict__ post_length)
{
    extern __shared__ float sm[];                      // Ll*Bb floats = 64KB
    int s = blockIdx.x;
    float* base = attn + (size_t)s * Ll * Bb;
    for (int i = threadIdx.x; i < Ll * Bb; i += blockDim.x) sm[i] = base[i];
    __syncthreads();
    int b = threadIdx.x;
    if (b < Bb) {
        int plen = post_length[b];
        float m = -INFINITY;
        for (int l = 0; l < plen; l++) m = fmaxf(m, sm[l * Bb + b]);
        float sum = 0.f;
        for (int l = 0; l < plen; l++) {
            float e = expf(sm[l * Bb + b] - m);
            sm[l * Bb + b] = e;
            sum += e;
        }
        float inv = 1.f / sum;
        for (int l = 0; l < plen; l++) sm[l * Bb + b] *= inv;
        for (int l = plen; l < Ll; l++) sm[l * Bb + b] = 0.f;
    }
    __syncthreads();
    for (int i = threadIdx.x; i < Ll * Bb; i += blockDim.x) base[i] = sm[i];
}

__global__ void copy_hlast_kernel(float* __restrict__ out) {
    int idx = blockIdx.x * blockDim.x + threadIdx.x;
    out[idx] = g_h[idx];
}

// ---------------- launcher ----------------
extern "C" void kernel_launch(void* const* d_in, const int* in_sizes, int n_in,
                              void* d_out, int out_size)
{
    (void)in_sizes; (void)n_in; (void)out_size;
    const float* incoming = (const float*)d_in[0];   // [S,B,I]
    const float* post     = (const float*)d_in[1];   // [L,B,P]
    const float* h_init   = (const float*)d_in[2];   // [1,1,H]
    const float* W_ih     = (const float*)d_in[3];   // [3H,I]
    const float* W_hh     = (const float*)d_in[4];   // [3H,H]
    const float* b_ih     = (const float*)d_in[5];   // [3H]
    const float* b_hh     = (const float*)d_in[6];   // [3H]
    const float* Wq       = (const float*)d_in[7];   // [P,H]
    const float* bq       = (const float*)d_in[8];   // [P]
    const int*   length   = (const int*)d_in[9];     // [B]
    const int*   plen     = (const int*)d_in[10];    // [B]

    float* out    = (float*)d_out;
    float* h_last = out;                                       // [B,H]
    float* hs     = out + (size_t)Bb * Hh;                     // [S,B,2H]
    float* attn   = hs + (size_t)Ss * Bb * 2048;               // [S,L,B]

    float *GI, *Q;
    bf16 *inch, *incl, *WihH, *WihL, *WhhH, *WhhL, *WqH, *WqL;
    bf16 *chH, *chL, *hsH, *hsL;
    cudaGetSymbolAddress((void**)&GI,   g_GI);
    cudaGetSymbolAddress((void**)&Q,    g_Q);
    cudaGetSymbolAddress((void**)&inch, g_inch);
    cudaGetSymbolAddress((void**)&incl, g_incl);
    cudaGetSymbolAddress((void**)&WihH, g_Wih_h);
    cudaGetSymbolAddress((void**)&WihL, g_Wih_l);
    cudaGetSymbolAddress((void**)&WhhH, g_Whh_h);
    cudaGetSymbolAddress((void**)&WhhL, g_Whh_l);
    cudaGetSymbolAddress((void**)&WqH,  g_Wq_h);
    cudaGetSymbolAddress((void**)&WqL,  g_Wq_l);
    cudaGetSymbolAddress((void**)&chH,  g_ch_h);
    cudaGetSymbolAddress((void**)&chL,  g_ch_l);
    cudaGetSymbolAddress((void**)&hsH,  g_hsh);
    cudaGetSymbolAddress((void**)&hsL,  g_hsl);

    cudaFuncSetAttribute(softmax_kernel,
                         cudaFuncAttributeMaxDynamicSharedMemorySize, 65536);

    // 0) conversions
    split_kernel<<<(Ss*Bb*Ii + 255)/256, 256>>>(incoming, inch, incl, Ss*Bb*Ii);
    split_kernel<<<(H3*Ii + 255)/256, 256>>>(W_ih, WihH, WihL, H3*Ii);
    split_kernel<<<(H3*Hh + 255)/256, 256>>>(W_hh, WhhH, WhhL, H3*Hh);
    split_kernel<<<(Pp*Hh + 255)/256, 256>>>(Wq, WqH, WqL, Pp*Hh);
    init_h_kernel<<<256, 256>>>(h_init);

    // 1) GI = incoming @ W_ih^T  (bias folded into scan)
    wmma_nt_split<<<dim3(Ss*Bb/WBM, H3/WBN), 256>>>(
        inch, incl, Ii, WihH, WihL, Ii, GI, H3, Ii);

    // 2) fused scan: per-step MMA + GRU (h split ping-pong)
    for (int t = 0; t < Ss; t++) {
        const bf16* hinH = chH + (t & 1) * (Bb * Hh);
        const bf16* hinL = chL + (t & 1) * (Bb * Hh);
        bf16* houtH = chH + ((t + 1) & 1) * (Bb * Hh);
        bf16* houtL = chL + ((t + 1) & 1) * (Bb * Hh);
        gru_scan_step<<<128, 128>>>(t, hinH, hinL, houtH, houtL,
                                    b_ih, b_hh, length, hs);
    }

    // 3) Q = h_history @ Wq^T, then + bq
    wmma_nt_split<<<dim3(Ss*Bb/WBM, Pp/WBN), 256>>>(
        hsH, hsL, Hh, WqH, WqL, Hh, Q, Pp, Hh);
    biasq_kernel<<<(Ss*Bb*Pp + 255)/256, 256>>>(bq);

    // 4) scores[s,l,b] = Q_b[s,:] . post_b[l,:]
    gemm_nt<128,128,8,8,8><<<dim3(Ss/128, Ll/128, Bb), 256>>>(
        Q, Bb*Pp, Pp,  post, Bb*Pp, Pp,
        attn, Ll*Bb, Bb, 1,  nullptr,  Ss, Ll, Pp, 0);

    // 5) masked softmax over l, in place
    softmax_kernel<<<Ss, 256, Ll*Bb*sizeof(float)>>>(attn, plen);

    // 6) context[s,b,:] = attn_b[s,:] @ post_b  -> hs[:, :, H:2H]
    gemm_nn<64,64,16,4,4><<<dim3(Ss/64, Pp/64, Bb), 256>>>(
        attn, Ll*Bb, Bb, 1,   post, Bb*Pp, Pp,
        hs + Hh, Bb*2048, 2048,  Ss, Pp, Ll);

    // 7) h_last
    copy_hlast_kernel<<<256, 256>>>(h_last);
}

// round 5
// speedup vs baseline: 2.5076x; 2.5076x over previous
#include <cuda_runtime.h>
#include <cuda_bf16.h>
#include <mma.h>
#include <math.h>

using namespace nvcuda;
typedef __nv_bfloat16 bf16;

#define Ss 256
#define Bb 64
#define Ii 1024
#define Hh 1024
#define H3 3072
#define Pp 1024
#define Ll 256
#define SCAN_BLOCKS 128

// ---------------- scratch (static device allocations) ----------------
__device__ float g_GI[(size_t)Ss * Bb * H3];
__device__ float g_Q [(size_t)Ss * Bb * Pp];
__device__ bf16 g_inch[(size_t)Ss * Bb * Ii], g_incl[(size_t)Ss * Bb * Ii];
__device__ bf16 g_Wih_h[(size_t)H3 * Ii],  g_Wih_l[(size_t)H3 * Ii];
__device__ bf16 g_Whh_h[(size_t)H3 * Hh],  g_Whh_l[(size_t)H3 * Hh];
__device__ bf16 g_Wq_h [(size_t)Pp * Hh],  g_Wq_l [(size_t)Pp * Hh];
__device__ bf16 g_Qh[(size_t)Ss * Bb * Pp], g_Ql[(size_t)Ss * Bb * Pp];
__device__ bf16 g_ph[(size_t)Ll * Bb * Pp], g_pl[(size_t)Ll * Bb * Pp];
__device__ bf16 g_ch_h[2][Bb * Hh], g_ch_l[2][Bb * Hh];   // h split ping-pong
__device__ bf16 g_hsh[(size_t)Ss * Bb * Hh], g_hsl[(size_t)Ss * Bb * Hh];
__device__ unsigned g_count;     // monotonic arrival counter (reset per launch)

// ---------------- cp.async helpers ----------------
__device__ __forceinline__ void cpasync16(void* dst, const void* src) {
    unsigned d = (unsigned)__cvta_generic_to_shared(dst);
    asm volatile("cp.async.cg.shared.global [%0], [%1], 16;\n" :: "r"(d), "l"(src));
}
__device__ __forceinline__ void cpcommit() { asm volatile("cp.async.commit_group;\n"); }
template<int N> __device__ __forceinline__ void cpwait() {
    asm volatile("cp.async.wait_group %0;\n" :: "n"(N));
}

// ---------------- split fp32 -> (hi, lo) bf16 ----------------
__global__ void split_kernel(const float* __restrict__ x,
                             bf16* __restrict__ hi, bf16* __restrict__ lo, int n)
{
    int i = blockIdx.x * blockDim.x + threadIdx.x;
    if (i < n) {
        float v = x[i];
        bf16 h = __float2bfloat16(v);
        hi[i] = h;
        lo[i] = __float2bfloat16(v - __bfloat162float(h));
    }
}

// ---------------- pipelined split-bf16 NT GEMM: C = A * B^T ----------------
// 128x128 block tile, BK=32, 2-stage cp.async double buffer, 256 thr / 8 warps.
__global__ void __launch_bounds__(256)
wmma_split_nt(const bf16* __restrict__ Ah, const bf16* __restrict__ Al,
              long ldaR, long batchA,
              const bf16* __restrict__ Bh, const bf16* __restrict__ Bl,
              long ldbR, long batchB,
              float* __restrict__ C, long ldcR, long cstr, long batchC,
              int K)
{
    extern __shared__ bf16 sm[];
    const int LD = 40;                         // 32 + 8 pad
    int z = blockIdx.z;
    Ah += (size_t)z * batchA;  Al += (size_t)z * batchA;
    Bh += (size_t)z * batchB;  Bl += (size_t)z * batchB;
    C  += (size_t)z * batchC;
    int m0 = blockIdx.x * 128, n0 = blockIdx.y * 128;
    int tid = threadIdx.x;
    int w = tid >> 5, wr = w >> 2, wc = w & 3;

    wmma::fragment<wmma::accumulator,16,16,16,float> acc[4][2];
#pragma unroll
    for (int i = 0; i < 4; i++)
#pragma unroll
        for (int j = 0; j < 2; j++) wmma::fill_fragment(acc[i][j], 0.f);

    auto issue = [&](int kt, int stg) {
        bf16* base = sm + (size_t)stg * 4 * 128 * LD;
        int k0 = kt * 32;
#pragma unroll
        for (int i = 0; i < 8; i++) {
            int id = tid + 256 * i;            // 0..2047
            int buf = id >> 9;                 // 0:Ah 1:Al 2:Bh 3:Bl
            int e = id & 511;
            int r = e >> 2, c = (e & 3) * 8;
            const bf16* src;
            if      (buf == 0) src = Ah + (size_t)(m0 + r) * ldaR + k0 + c;
            else if (buf == 1) src = Al + (size_t)(m0 + r) * ldaR + k0 + c;
            else if (buf == 2) src = Bh + (size_t)(n0 + r) * ldbR + k0 + c;
            else               src = Bl + (size_t)(n0 + r) * ldbR + k0 + c;
            cpasync16(base + (size_t)buf * 128 * LD + r * LD + c, src);
        }
        cpcommit();
    };

    int KT = K / 32;
    issue(0, 0);
    for (int kt = 0; kt < KT; kt++) {
        if (kt + 1 < KT) { issue(kt + 1, (kt + 1) & 1); cpwait<1>(); }
        else             { cpwait<0>(); }
        __syncthreads();
        bf16* base = sm + (size_t)(kt & 1) * 4 * 128 * LD;
        bf16 *sAh_ = base, *sAl_ = base + 128*LD, *sBh_ = base + 2*128*LD, *sBl_ = base + 3*128*LD;
#pragma unroll
        for (int ks = 0; ks < 2; ks++) {
            wmma::fragment<wmma::matrix_a,16,16,16,bf16,wmma::row_major> ah[4], al[4];
            wmma::fragment<wmma::matrix_b,16,16,16,bf16,wmma::col_major> bh[2], bl[2];
#pragma unroll
            for (int i = 0; i < 4; i++) {
                wmma::load_matrix_sync(ah[i], sAh_ + (wr*64 + i*16)*LD + ks*16, LD);
                wmma::load_matrix_sync(al[i], sAl_ + (wr*64 + i*16)*LD + ks*16, LD);
            }
#pragma unroll
            for (int j = 0; j < 2; j++) {
                wmma::load_matrix_sync(bh[j], sBh_ + (wc*32 + j*16)*LD + ks*16, LD);
                wmma::load_matrix_sync(bl[j], sBl_ + (wc*32 + j*16)*LD + ks*16, LD);
            }
#pragma unroll
            for (int i = 0; i < 4; i++)
#pragma unroll
                for (int j = 0; j < 2; j++) {
                    wmma::mma_sync(acc[i][j], ah[i], bh[j], acc[i][j]);
                    wmma::mma_sync(acc[i][j], ah[i], bl[j], acc[i][j]);
                    wmma::mma_sync(acc[i][j], al[i], bh[j], acc[i][j]);
                }
        }
        __syncthreads();
    }

    if (cstr == 1) {
#pragma unroll
        for (int i = 0; i < 4; i++)
#pragma unroll
            for (int j = 0; j < 2; j++)
                wmma::store_matrix_sync(
                    C + (size_t)(m0 + wr*64 + i*16) * ldcR + n0 + wc*32 + j*16,
                    acc[i][j], ldcR, wmma::mem_row_major);
    } else {
        float* smf = (float*)sm;
        __syncthreads();
#pragma unroll
        for (int i = 0; i < 4; i++)
#pragma unroll
            for (int j = 0; j < 2; j++)
                wmma::store_matrix_sync(smf + (wr*64 + i*16)*128 + wc*32 + j*16,
                                        acc[i][j], 128, wmma::mem_row_major);
        __syncthreads();
        for (int e = tid; e < 16384; e += 256) {
            int m = e >> 7, n = e & 127;
            C[(size_t)(m0 + m) * ldcR + (size_t)(n0 + n) * cstr] = smf[e];
        }
    }
}

// ---------------- persistent GRU scan ----------------
// 128 blocks x 256 thr. Block owns 8 units; its 24 W_hh rows (hi+lo) stay in
// SMEM for all 256 steps. h carried in registers; h-splits ping-pong through
// global with cp.async.cg (L1 bypass). Grid barrier = monotonic counter.
__global__ void __launch_bounds__(256)
gru_scan(const float* __restrict__ bih, const float* __restrict__ bhh,
         const int* __restrict__ length, const float* __restrict__ h_init,
         float* __restrict__ hs)
{
    extern __shared__ bf16 ssm[];
    const int WLD = 1032, ALD = 72;
    bf16* sWh = ssm;                       // 32 x 1032
    bf16* sWl = sWh + 32 * WLD;
    bf16* sA  = sWl + 32 * WLD;            // 2 stages x (hi 64x72 + lo 64x72)
    float* ghsm = (float*)sA;              // reused after MMA: 64 x 36 floats

    int tid = threadIdx.x;
    int w = tid >> 5, wr = w & 3, wc = w >> 2;   // 4 M-strips x 2 N-strips
    int j0 = blockIdx.x * 8;

    // zero W smem (pad rows 24..31 + pad cols), then load 24 real rows
    for (int i = tid; i < 32 * WLD; i += 256) {
        sWh[i] = __float2bfloat16(0.f);
        sWl[i] = __float2bfloat16(0.f);
    }
    __syncthreads();
    for (int i = tid; i < 24 * 128; i += 256) {
        int rb = i >> 7, c = (i & 127) * 8;
        size_t wrow = (size_t)((rb >> 3) * 1024 + j0 + (rb & 7));
        *(uint4*)(sWh + rb * WLD + c) = *(const uint4*)(g_Whh_h + wrow * Hh + c);
        *(uint4*)(sWl + rb * WLD + c) = *(const uint4*)(g_Whh_l + wrow * Hh + c);
    }

    // per-thread GRU state: unit u, batches bA and bA+32
    int u = tid & 7, bA = tid >> 3;
    float hp0 = h_init[j0 + u], hp1 = hp0;
    int len0 = length[bA], len1 = length[bA + 32];
    float br = bhh[j0+u], bz = bhh[Hh+j0+u], bn = bhh[2*Hh+j0+u];
    float cr = bih[j0+u], cz = bih[Hh+j0+u], cn = bih[2*Hh+j0+u];
    __syncthreads();

    for (int t = 0; t < Ss; t++) {
        const bf16* hinH = &g_ch_h[t & 1][0];
        const bf16* hinL = &g_ch_l[t & 1][0];
        bf16* houtH = &g_ch_h[(t + 1) & 1][0];
        bf16* houtL = &g_ch_l[(t + 1) & 1][0];

        wmma::fragment<wmma::accumulator,16,16,16,float> acc;
        wmma::fill_fragment(acc, 0.f);

        auto issueA = [&](int kc, int stg) {
            bf16* dh = sA + (size_t)stg * 2 * 64 * ALD;
            bf16* dl = dh + 64 * ALD;
#pragma unroll
            for (int i = 0; i < 4; i++) {
                int id = tid + 256 * i;          // 0..1023
                int half = id >> 9;
                int e = id & 511;
                int r = e >> 3, c = (e & 7) * 8;
                const bf16* src = (half ? hinL : hinH) + r * Hh + kc * 64 + c;
                cpasync16((half ? dl : dh) + r * ALD + c, src);
            }
            cpcommit();
        };

        issueA(0, 0);
        for (int kc = 0; kc < 16; kc++) {
            if (kc + 1 < 16) { issueA(kc + 1, (kc + 1) & 1); cpwait<1>(); }
            else             { cpwait<0>(); }
            __syncthreads();
            bf16* dh = sA + (size_t)(kc & 1) * 2 * 64 * ALD;
            bf16* dl = dh + 64 * ALD;
#pragma unroll
            for (int ks = 0; ks < 4; ks++) {
                wmma::fragment<wmma::matrix_a,16,16,16,bf16,wmma::row_major> ah, al;
                wmma::fragment<wmma::matrix_b,16,16,16,bf16,wmma::col_major> bhf, blf;
                wmma::load_matrix_sync(ah, dh + (wr*16)*ALD + ks*16, ALD);
                wmma::load_matrix_sync(al, dl + (wr*16)*ALD + ks*16, ALD);
                wmma::load_matrix_sync(bhf, sWh + (wc*16)*WLD + kc*64 + ks*16, WLD);
                wmma::load_matrix_sync(blf, sWl + (wc*16)*WLD + kc*64 + ks*16, WLD);
                wmma::mma_sync(acc, ah, bhf, acc);
                wmma::mma_sync(acc, ah, blf, acc);
                wmma::mma_sync(acc, al, bhf, acc);
            }
            __syncthreads();
        }

        // stage gh (64 batches x 32 cols: r at 0-7, z at 8-15, n at 16-23)
        wmma::store_matrix_sync(ghsm + (wr*16)*36 + wc*16, acc, 36, wmma::mem_row_major);
        __syncthreads();

#pragma unroll
        for (int e2 = 0; e2 < 2; e2++) {
            int b = bA + e2 * 32;
            float hprev = e2 ? hp1 : hp0;
            int   len   = e2 ? len1 : len0;
            float ghr = ghsm[b*36 + u]      + br;
            float ghz = ghsm[b*36 + 8 + u]  + bz;
            float ghn = ghsm[b*36 + 16 + u] + bn;
            const float* GIt = g_GI + ((size_t)t * Bb + b) * H3 + j0 + u;
            float gir = GIt[0]     + cr;
            float giz = GIt[Hh]    + cz;
            float gin = GIt[2*Hh]  + cn;
            float rg = 1.f / (1.f + expf(-(gir + ghr)));
            float zg = 1.f / (1.f + expf(-(giz + ghz)));
            float ng = tanhf(gin + rg * ghn);
            float keep = (t < len) ? 1.f : 0.f;
            float hn = (ng + zg * (hprev - ng)) * keep;
            if (e2) hp1 = hn; else hp0 = hn;

            int j = j0 + u;
            bf16 hhi = __float2bfloat16(hn);
            bf16 hlo = __float2bfloat16(hn - __bfloat162float(hhi));
            houtH[b*Hh + j] = hhi;
            houtL[b*Hh + j] = hlo;
            size_t hx = ((size_t)t * Bb + b) * Hh + j;
            g_hsh[hx] = hhi;
            g_hsl[hx] = hlo;
            hs[((size_t)t * Bb + b) * 2048 + j] = hn;
        }

        // monotonic-counter grid barrier (no resets -> no reset races)
        if (t < Ss - 1) {
            __syncthreads();
            if (tid == 0) {
                __threadfence();
                atomicAdd(&g_count, 1u);
                unsigned target = (unsigned)(t + 1) * SCAN_BLOCKS;
                while (*(volatile unsigned*)&g_count < target)
                    __nanosleep(64);
                __threadfence();
            }
            __syncthreads();
        }
    }
}

// ---------------- fp32 NN GEMM (context) ----------------
template<int BM,int BN,int BK,int TM,int TN>
__global__ void __launch_bounds__((BM/TM)*(BN/TN))
gemm_nn(const float* __restrict__ A, int ldaR, int ldaE, int batchA,
        const float* __restrict__ B, int ldb, int batchB,
        float* __restrict__ C, int ldc, int batchC,
        int M, int N, int K)
{
    constexpr int TH = (BM/TM)*(BN/TN);
    __shared__ float As[BK][BM];
    __shared__ float Bs[BK][BN];

    int z = blockIdx.z;
    A += (size_t)z * batchA;
    B += (size_t)z * batchB;
    C += (size_t)z * batchC;

    int m0 = blockIdx.x * BM, n0 = blockIdx.y * BN;
    int tid = threadIdx.x;
    int tx = tid % (BN/TN), ty = tid / (BN/TN);

    float acc[TM][TN];
#pragma unroll
    for (int i = 0; i < TM; i++)
#pragma unroll
        for (int j = 0; j < TN; j++) acc[i][j] = 0.f;

    for (int k0 = 0; k0 < K; k0 += BK) {
#pragma unroll
        for (int e = tid; e < BM*BK; e += TH) {
            int m = e / BK, k = e % BK;
            As[k][m] = A[(size_t)(m0 + m) * ldaR + (size_t)(k0 + k) * ldaE];
        }
        {
            constexpr int V = BN * BK / 4;
#pragma unroll
            for (int v = tid; v < V; v += TH) {
                int n4 = v % (BN/4);
                int k  = v / (BN/4);
                float4 b = *reinterpret_cast<const float4*>(
                    B + (size_t)(k0 + k) * ldb + n0 + n4 * 4);
                Bs[k][n4*4+0] = b.x; Bs[k][n4*4+1] = b.y;
                Bs[k][n4*4+2] = b.z; Bs[k][n4*4+3] = b.w;
            }
        }
        __syncthreads();
#pragma unroll
        for (int k = 0; k < BK; k++) {
            float fa[TM], fb[TN];
#pragma unroll
            for (int i = 0; i < TM; i++) fa[i] = As[k][ty*TM + i];
#pragma unroll
            for (int j = 0; j < TN; j++) fb[j] = Bs[k][tx*TN + j];
#pragma unroll
            for (int i = 0; i < TM; i++)
#pragma unroll
                for (int j = 0; j < TN; j++)
                    acc[i][j] += fa[i] * fb[j];
        }
        __syncthreads();
    }

#pragma unroll
    for (int i = 0; i < TM; i++) {
        int m = m0 + ty*TM + i;
#pragma unroll
        for (int j = 0; j < TN; j++) {
            int n = n0 + tx*TN + j;
            C[(size_t)m * ldc + n] = acc[i][j];
        }
    }
}

// ---------------- small kernels ----------------
__global__ void init_h_kernel(const float* __restrict__ h_init) {
    int idx = blockIdx.x * blockDim.x + threadIdx.x;   // 65536
    float v = h_init[idx & (Hh - 1)];
    bf16 hi = __float2bfloat16(v);
    g_ch_h[0][idx] = hi;
    g_ch_l[0][idx] = __float2bfloat16(v - __bfloat162float(hi));
    if (idx == 0) g_count = 0;
}

__global__ void biasq_kernel(const float* __restrict__ bq) {
    int idx = blockIdx.x * blockDim.x + threadIdx.x;
    g_Q[idx] += bq[idx & (Pp - 1)];
}

__global__ void softmax_kernel(float* __restrict__ attn,
                               const int* __restrict__ post_length)
{
    extern __shared__ float smf[];                     // Ll*Bb floats = 64KB
    int s = blockIdx.x;
    float* base = attn + (size_t)s * Ll * Bb;
    for (int i = threadIdx.x; i < Ll * Bb; i += blockDim.x) smf[i] = base[i];
    __syncthreads();
    int b = threadIdx.x;
    if (b < Bb) {
        int plen = post_length[b];
        float m = -INFINITY;
        for (int l = 0; l < plen; l++) m = fmaxf(m, smf[l * Bb + b]);
        float sum = 0.f;
        for (int l = 0; l < plen; l++) {
            float e = expf(smf[l * Bb + b] - m);
            smf[l * Bb + b] = e;
            sum += e;
        }
        float inv = 1.f / sum;
        for (int l = 0; l < plen; l++) smf[l * Bb + b] *= inv;
        for (int l = plen; l < Ll; l++) smf[l * Bb + b] = 0.f;
    }
    __syncthreads();
    for (int i = threadIdx.x; i < Ll * Bb; i += blockDim.x) base[i] = smf[i];
}

__global__ void copy_hlast_kernel(const float* __restrict__ hs, float* __restrict__ out) {
    int idx = blockIdx.x * blockDim.x + threadIdx.x;   // 65536
    int b = idx >> 10, j = idx & 1023;
    out[idx] = hs[((size_t)255 * Bb + b) * 2048 + j];
}

// ---------------- launcher ----------------
extern "C" void kernel_launch(void* const* d_in, const int* in_sizes, int n_in,
                              void* d_out, int out_size)
{
    (void)in_sizes; (void)n_in; (void)out_size;
    const float* incoming = (const float*)d_in[0];
    const float* post     = (const float*)d_in[1];
    const float* h_init   = (const float*)d_in[2];
    const float* W_ih     = (const float*)d_in[3];
    const float* W_hh     = (const float*)d_in[4];
    const float* b_ih     = (const float*)d_in[5];
    const float* b_hh     = (const float*)d_in[6];
    const float* Wq       = (const float*)d_in[7];
    const float* bq       = (const float*)d_in[8];
    const int*   length   = (const int*)d_in[9];
    const int*   plen     = (const int*)d_in[10];

    float* out    = (float*)d_out;
    float* h_last = out;
    float* hs     = out + (size_t)Bb * Hh;
    float* attn   = hs + (size_t)Ss * Bb * 2048;

    float *GI, *Q;
    bf16 *inch, *incl, *WihH, *WihL, *WqH, *WqL, *Qh, *Ql, *ph, *pl, *hsH, *hsL;
    bf16 *WhhH, *WhhL;
    cudaGetSymbolAddress((void**)&GI,   g_GI);
    cudaGetSymbolAddress((void**)&Q,    g_Q);
    cudaGetSymbolAddress((void**)&inch, g_inch);
    cudaGetSymbolAddress((void**)&incl, g_incl);
    cudaGetSymbolAddress((void**)&WihH, g_Wih_h);
    cudaGetSymbolAddress((void**)&WihL, g_Wih_l);
    cudaGetSymbolAddress((void**)&WhhH, g_Whh_h);
    cudaGetSymbolAddress((void**)&WhhL, g_Whh_l);
    cudaGetSymbolAddress((void**)&WqH,  g_Wq_h);
    cudaGetSymbolAddress((void**)&WqL,  g_Wq_l);
    cudaGetSymbolAddress((void**)&Qh,   g_Qh);
    cudaGetSymbolAddress((void**)&Ql,   g_Ql);
    cudaGetSymbolAddress((void**)&ph,   g_ph);
    cudaGetSymbolAddress((void**)&pl,   g_pl);
    cudaGetSymbolAddress((void**)&hsH,  g_hsh);
    cudaGetSymbolAddress((void**)&hsL,  g_hsl);

    const int GEMM_SMEM = 2 * 4 * 128 * 40 * (int)sizeof(bf16);        // 81920
    const int SCAN_SMEM = (2*32*1032 + 2*2*64*72) * (int)sizeof(bf16); // 168960
    cudaFuncSetAttribute(wmma_split_nt,
                         cudaFuncAttributeMaxDynamicSharedMemorySize, GEMM_SMEM);
    cudaFuncSetAttribute(gru_scan,
                         cudaFuncAttributeMaxDynamicSharedMemorySize, SCAN_SMEM);
    cudaFuncSetAttribute(softmax_kernel,
                         cudaFuncAttributeMaxDynamicSharedMemorySize, 65536);

    // 0) splits + init
    split_kernel<<<(Ss*Bb*Ii + 255)/256, 256>>>(incoming, inch, incl, Ss*Bb*Ii);
    split_kernel<<<(H3*Ii + 255)/256, 256>>>(W_ih, WihH, WihL, H3*Ii);
    split_kernel<<<(H3*Hh + 255)/256, 256>>>(W_hh, WhhH, WhhL, H3*Hh);
    split_kernel<<<(Pp*Hh + 255)/256, 256>>>(Wq, WqH, WqL, Pp*Hh);
    split_kernel<<<(Ll*Bb*Pp + 255)/256, 256>>>(post, ph, pl, Ll*Bb*Pp);
    init_h_kernel<<<256, 256>>>(h_init);

    // 1) GI = incoming @ W_ih^T
    wmma_split_nt<<<dim3(Ss*Bb/128, H3/128, 1), 256, GEMM_SMEM>>>(
        inch, incl, Ii, 0,  WihH, WihL, Ii, 0,
        GI, H3, 1, 0,  Ii);

    // 2) persistent scan (one launch, 256 steps)
    gru_scan<<<SCAN_BLOCKS, 256, SCAN_SMEM>>>(b_ih, b_hh, length, h_init, hs);

    // 3) Q = h_hist @ Wq^T, + bq, then split
    wmma_split_nt<<<dim3(Ss*Bb/128, Pp/128, 1), 256, GEMM_SMEM>>>(
        hsH, hsL, Hh, 0,  WqH, WqL, Hh, 0,
        Q, Pp, 1, 0,  Hh);
    biasq_kernel<<<(Ss*Bb*Pp + 255)/256, 256>>>(bq);
    split_kernel<<<(Ss*Bb*Pp + 255)/256, 256>>>(Q, Qh, Ql, Ss*Bb*Pp);

    // 4) scores[s,l,b] = Q_b[s,:] . post_b[l,:]  (batched over b)
    wmma_split_nt<<<dim3(Ss/128, Ll/128, Bb), 256, GEMM_SMEM>>>(
        Qh, Ql, (long)Bb*Pp, Pp,  ph, pl, (long)Bb*Pp, Pp,
        attn, (long)Ll*Bb, Bb, 1,  Pp);

    // 5) masked softmax over l
    softmax_kernel<<<Ss, 256, Ll*Bb*sizeof(float)>>>(attn, plen);

    // 6) context -> hs[:, :, H:2H]
    gemm_nn<64,64,16,4,4><<<dim3(Ss/64, Pp/64, Bb), 256>>>(
        attn, Ll*Bb, Bb, 1,   post, Bb*Pp, Pp,
        hs + Hh, Bb*2048, 2048,  Ss, Pp, Ll);

    // 7) h_last
    copy_hlast_kernel<<<256, 256>>>(hs, h_last);
}

// round 7
// speedup vs baseline: 2.5684x; 1.0242x over previous
#include <cuda_runtime.h>
#include <cuda_bf16.h>
#include <mma.h>
#include <math.h>

using namespace nvcuda;
typedef __nv_bfloat16 bf16;

#define Ss 256
#define Bb 64
#define Ii 1024
#define Hh 1024
#define H3 3072
#define Pp 1024
#define Ll 256
#define SCAN_BLOCKS 128

// ---------------- scratch (static device allocations) ----------------
__device__ float g_GI[(size_t)Ss * Bb * H3];
__device__ bf16 g_inch[(size_t)Ss * Bb * Ii], g_incl[(size_t)Ss * Bb * Ii];
__device__ bf16 g_Wih_h[(size_t)H3 * Ii],  g_Wih_l[(size_t)H3 * Ii];
__device__ bf16 g_Whh_h[(size_t)H3 * Hh],  g_Whh_l[(size_t)H3 * Hh];
__device__ bf16 g_Wq_h [(size_t)Pp * Hh],  g_Wq_l [(size_t)Pp * Hh];
__device__ bf16 g_Qh[(size_t)Ss * Bb * Pp], g_Ql[(size_t)Ss * Bb * Pp];
__device__ bf16 g_ph[(size_t)Ll * Bb * Pp], g_pl[(size_t)Ll * Bb * Pp];
__device__ bf16 g_ah[(size_t)Bb * Ss * Ll], g_al[(size_t)Bb * Ss * Ll];  // attn split [b][s][l]
__device__ bf16 g_ch_h[2][Bb * Hh], g_ch_l[2][Bb * Hh];   // h split ping-pong
__device__ bf16 g_hsh[(size_t)Ss * Bb * Hh], g_hsl[(size_t)Ss * Bb * Hh];
__device__ unsigned g_count;     // monotonic arrival counter (reset per launch)

// ---------------- cp.async helpers ----------------
__device__ __forceinline__ void cpasync16(void* dst, const void* src) {
    unsigned d = (unsigned)__cvta_generic_to_shared(dst);
    asm volatile("cp.async.cg.shared.global [%0], [%1], 16;\n" :: "r"(d), "l"(src));
}
__device__ __forceinline__ void cpcommit() { asm volatile("cp.async.commit_group;\n"); }
template<int N> __device__ __forceinline__ void cpwait() {
    asm volatile("cp.async.wait_group %0;\n" :: "n"(N));
}

// ---------------- split fp32 -> (hi, lo) bf16 ----------------
__global__ void split_kernel(const float* __restrict__ x,
                             bf16* __restrict__ hi, bf16* __restrict__ lo, int n)
{
    int i = blockIdx.x * blockDim.x + threadIdx.x;
    if (i < n) {
        float v = x[i];
        bf16 h = __float2bfloat16(v);
        hi[i] = h;
        lo[i] = __float2bfloat16(v - __bfloat162float(h));
    }
}

// ---------------- pipelined split-bf16 NT GEMM: C = A * B^T ----------------
// 128x128 tile, BK=32, 2-stage cp.async, 256 thr / 8 warps, warp tile 64x32.
// Epilogue modes: (a) Ch!=null: bias add + split-bf16 output; (b) cstr==1:
// direct fp32 store; (c) strided fp32 store via smem.
__global__ void __launch_bounds__(256)
wmma_split_nt(const bf16* __restrict__ Ah, const bf16* __restrict__ Al,
              long ldaR, long batchA,
              const bf16* __restrict__ Bh, const bf16* __restrict__ Bl,
              long ldbR, long batchB,
              float* __restrict__ C, long ldcR, long cstr, long batchC,
              const float* __restrict__ bias,
              bf16* __restrict__ Ch, bf16* __restrict__ Cl,
              int K)
{
    extern __shared__ bf16 sm[];
    const int LD = 40;                         // 32 + 8 pad
    int z = blockIdx.z;
    Ah += (size_t)z * batchA;  Al += (size_t)z * batchA;
    Bh += (size_t)z * batchB;  Bl += (size_t)z * batchB;
    if (C) C += (size_t)z * batchC;
    int m0 = blockIdx.x * 128, n0 = blockIdx.y * 128;
    int tid = threadIdx.x;
    int w = tid >> 5, wr = w >> 2, wc = w & 3;

    wmma::fragment<wmma::accumulator,16,16,16,float> acc[4][2];
#pragma unroll
    for (int i = 0; i < 4; i++)
#pragma unroll
        for (int j = 0; j < 2; j++) wmma::fill_fragment(acc[i][j], 0.f);

    auto issue = [&](int kt, int stg) {
        bf16* base = sm + (size_t)stg * 4 * 128 * LD;
        int k0 = kt * 32;
#pragma unroll
        for (int i = 0; i < 8; i++) {
            int id = tid + 256 * i;            // 0..2047
            int buf = id >> 9;                 // 0:Ah 1:Al 2:Bh 3:Bl
            int e = id & 511;
            int r = e >> 2, c = (e & 3) * 8;
            const bf16* src;
            if      (buf == 0) src = Ah + (size_t)(m0 + r) * ldaR + k0 + c;
            else if (buf == 1) src = Al + (size_t)(m0 + r) * ldaR + k0 + c;
            else if (buf == 2) src = Bh + (size_t)(n0 + r) * ldbR + k0 + c;
            else               src = Bl + (size_t)(n0 + r) * ldbR + k0 + c;
            cpasync16(base + (size_t)buf * 128 * LD + r * LD + c, src);
        }
        cpcommit();
    };

    int KT = K / 32;
    issue(0, 0);
    for (int kt = 0; kt < KT; kt++) {
        if (kt + 1 < KT) { issue(kt + 1, (kt + 1) & 1); cpwait<1>(); }
        else             { cpwait<0>(); }
        __syncthreads();
        bf16* base = sm + (size_t)(kt & 1) * 4 * 128 * LD;
        bf16 *sAh_ = base, *sAl_ = base + 128*LD, *sBh_ = base + 2*128*LD, *sBl_ = base + 3*128*LD;
#pragma unroll
        for (int ks = 0; ks < 2; ks++) {
            wmma::fragment<wmma::matrix_a,16,16,16,bf16,wmma::row_major> ah[4], al[4];
            wmma::fragment<wmma::matrix_b,16,16,16,bf16,wmma::col_major> bh[2], bl[2];
#pragma unroll
            for (int i = 0; i < 4; i++) {
                wmma::load_matrix_sync(ah[i], sAh_ + (wr*64 + i*16)*LD + ks*16, LD);
                wmma::load_matrix_sync(al[i], sAl_ + (wr*64 + i*16)*LD + ks*16, LD);
            }
#pragma unroll
            for (int j = 0; j < 2; j++) {
                wmma::load_matrix_sync(bh[j], sBh_ + (wc*32 + j*16)*LD + ks*16, LD);
                wmma::load_matrix_sync(bl[j], sBl_ + (wc*32 + j*16)*LD + ks*16, LD);
            }
#pragma unroll
            for (int i = 0; i < 4; i++)
#pragma unroll
                for (int j = 0; j < 2; j++) {
                    wmma::mma_sync(acc[i][j], ah[i], bh[j], acc[i][j]);
                    wmma::mma_sync(acc[i][j], ah[i], bl[j], acc[i][j]);
                    wmma::mma_sync(acc[i][j], al[i], bh[j], acc[i][j]);
                }
        }
        __syncthreads();
    }

    if (Ch) {
        // bias + split epilogue (row-major, ldcR)
        float* smf = (float*)sm;
        __syncthreads();
#pragma unroll
        for (int i = 0; i < 4; i++)
#pragma unroll
            for (int j = 0; j < 2; j++)
                wmma::store_matrix_sync(smf + (wr*64 + i*16)*128 + wc*32 + j*16,
                                        acc[i][j], 128, wmma::mem_row_major);
        __syncthreads();
        for (int e = tid; e < 16384; e += 256) {
            int m = e >> 7, n = e & 127;
            float v = smf[e] + (bias ? bias[n0 + n] : 0.f);
            bf16 hi = __float2bfloat16(v);
            size_t off = (size_t)(m0 + m) * ldcR + n0 + n;
            Ch[off] = hi;
            Cl[off] = __float2bfloat16(v - __bfloat162float(hi));
        }
    } else if (cstr == 1) {
#pragma unroll
        for (int i = 0; i < 4; i++)
#pragma unroll
            for (int j = 0; j < 2; j++)
                wmma::store_matrix_sync(
                    C + (size_t)(m0 + wr*64 + i*16) * ldcR + n0 + wc*32 + j*16,
                    acc[i][j], ldcR, wmma::mem_row_major);
    } else {
        float* smf = (float*)sm;
        __syncthreads();
#pragma unroll
        for (int i = 0; i < 4; i++)
#pragma unroll
            for (int j = 0; j < 2; j++)
                wmma::store_matrix_sync(smf + (wr*64 + i*16)*128 + wc*32 + j*16,
                                        acc[i][j], 128, wmma::mem_row_major);
        __syncthreads();
        for (int e = tid; e < 16384; e += 256) {
            int m = e >> 7, n = e & 127;
            C[(size_t)(m0 + m) * ldcR + (size_t)(n0 + n) * cstr] = smf[e];
        }
    }
}

// ---------------- split-bf16 NN GEMM: C = A * B (B row-major [K,N]) --------
// 128x128 tile, BK=32, 2-stage, 256 thr / 8 warps. Used for context.
__global__ void __launch_bounds__(256)
wmma_split_nn(const bf16* __restrict__ Ah, const bf16* __restrict__ Al,
              long ldaR, long batchA,
              const bf16* __restrict__ Bh, const bf16* __restrict__ Bl,
              long ldbR, long batchB,
              float* __restrict__ C, long ldcR, long batchC, int K)
{
    extern __shared__ bf16 sm[];
    const int ALD = 40, BLD = 136;
    const int STG = 2*128*ALD + 2*32*BLD;      // bf16 per stage = 18944
    int z = blockIdx.z;
    Ah += (size_t)z * batchA;  Al += (size_t)z * batchA;
    Bh += (size_t)z * batchB;  Bl += (size_t)z * batchB;
    C  += (size_t)z * batchC;
    int m0 = blockIdx.x * 128, n0 = blockIdx.y * 128;
    int tid = threadIdx.x;
    int w = tid >> 5, wr = w >> 2, wc = w & 3;

    wmma::fragment<wmma::accumulator,16,16,16,float> acc[4][2];
#pragma unroll
    for (int i = 0; i < 4; i++)
#pragma unroll
        for (int j = 0; j < 2; j++) wmma::fill_fragment(acc[i][j], 0.f);

    auto issue = [&](int kt, int stg) {
        bf16* base = sm + (size_t)stg * STG;
        bf16* dAh = base;
        bf16* dAl = base + 128*ALD;
        bf16* dBh = base + 2*128*ALD;
        bf16* dBl = dBh + 32*BLD;
        int k0 = kt * 32;
#pragma unroll
        for (int i = 0; i < 8; i++) {
            int id = tid + 256 * i;            // 0..2047
            int buf = id >> 9;
            int e = id & 511;
            if (buf < 2) {                     // A: 128 rows x 32 cols
                int r = e >> 2, c = (e & 3) * 8;
                const bf16* src = (buf ? Al : Ah) + (size_t)(m0 + r) * ldaR + k0 + c;
                cpasync16((buf ? dAl : dAh) + r * ALD + c, src);
            } else {                           // B: 32 rows x 128 cols
                int r = e >> 4, c = (e & 15) * 8;
                const bf16* src = (buf == 3 ? Bl : Bh) + (size_t)(k0 + r) * ldbR + n0 + c;
                cpasync16((buf == 3 ? dBl : dBh) + r * BLD + c, src);
            }
        }
        cpcommit();
    };

    int KT = K / 32;
    issue(0, 0);
    for (int kt = 0; kt < KT; kt++) {
        if (kt + 1 < KT) { issue(kt + 1, (kt + 1) & 1); cpwait<1>(); }
        else             { cpwait<0>(); }
        __syncthreads();
        bf16* base = sm + (size_t)(kt & 1) * STG;
        bf16* sAh_ = base;
        bf16* sAl_ = base + 128*ALD;
        bf16* sBh_ = base + 2*128*ALD;
        bf16* sBl_ = sBh_ + 32*BLD;
#pragma unroll
        for (int ks = 0; ks < 2; ks++) {
            wmma::fragment<wmma::matrix_a,16,16,16,bf16,wmma::row_major> ah[4], al[4];
            wmma::fragment<wmma::matrix_b,16,16,16,bf16,wmma::row_major> bh[2], bl[2];
#pragma unroll
            for (int i = 0; i < 4; i++) {
                wmma::load_matrix_sync(ah[i], sAh_ + (wr*64 + i*16)*ALD + ks*16, ALD);
                wmma::load_matrix_sync(al[i], sAl_ + (wr*64 + i*16)*ALD + ks*16, ALD);
            }
#pragma unroll
            for (int j = 0; j < 2; j++) {
                wmma::load_matrix_sync(bh[j], sBh_ + (ks*16)*BLD + wc*32 + j*16, BLD);
                wmma::load_matrix_sync(bl[j], sBl_ + (ks*16)*BLD + wc*32 + j*16, BLD);
            }
#pragma unroll
            for (int i = 0; i < 4; i++)
#pragma unroll
                for (int j = 0; j < 2; j++) {
                    wmma::mma_sync(acc[i][j], ah[i], bh[j], acc[i][j]);
                    wmma::mma_sync(acc[i][j], ah[i], bl[j], acc[i][j]);
                    wmma::mma_sync(acc[i][j], al[i], bh[j], acc[i][j]);
                }
        }
        __syncthreads();
    }
#pragma unroll
    for (int i = 0; i < 4; i++)
#pragma unroll
        for (int j = 0; j < 2; j++)
            wmma::store_matrix_sync(
                C + (size_t)(m0 + wr*64 + i*16) * ldcR + n0 + wc*32 + j*16,
                acc[i][j], ldcR, wmma::mem_row_major);
}

// ---------------- persistent GRU scan (4-stage, 1 sync per chunk) ----------
__global__ void __launch_bounds__(256)
gru_scan(const float* __restrict__ bih, const float* __restrict__ bhh,
         const int* __restrict__ length, const float* __restrict__ h_init,
         float* __restrict__ hs)
{
    extern __shared__ bf16 ssm[];
    const int WLD = 1032, ALD = 72;
    const int ASTG = 2 * 64 * ALD;             // 9216 bf16 per stage
    bf16* sWh = ssm;                           // 32 x 1032
    bf16* sWl = sWh + 32 * WLD;
    bf16* sA  = sWl + 32 * WLD;                // 4 stages
    float* ghsm = (float*)sA;                  // overlays stage 0 after MMA

    int tid = threadIdx.x;
    int w = tid >> 5, wr = w & 3, wc = w >> 2;   // 4 M-strips x 2 N-strips
    int j0 = blockIdx.x * 8;

    for (int i = tid; i < 32 * WLD; i += 256) {
        sWh[i] = __float2bfloat16(0.f);
        sWl[i] = __float2bfloat16(0.f);
    }
    __syncthreads();
    for (int i = tid; i < 24 * 128; i += 256) {
        int rb = i >> 7, c = (i & 127) * 8;
        size_t wrow = (size_t)((rb >> 3) * 1024 + j0 + (rb & 7));
        *(uint4*)(sWh + rb * WLD + c) = *(const uint4*)(g_Whh_h + wrow * Hh + c);
        *(uint4*)(sWl + rb * WLD + c) = *(const uint4*)(g_Whh_l + wrow * Hh + c);
    }

    int u = tid & 7, bA = tid >> 3;
    float hp0 = h_init[j0 + u], hp1 = hp0;
    int len0 = length[bA], len1 = length[bA + 32];
    float br = bhh[j0+u], bz = bhh[Hh+j0+u], bn = bhh[2*Hh+j0+u];
    float cr = bih[j0+u], cz = bih[Hh+j0+u], cn = bih[2*Hh+j0+u];
    __syncthreads();

    for (int t = 0; t < Ss; t++) {
        const bf16* hinH = &g_ch_h[t & 1][0];
        const bf16* hinL = &g_ch_l[t & 1][0];
        bf16* houtH = &g_ch_h[(t + 1) & 1][0];
        bf16* houtL = &g_ch_l[(t + 1) & 1][0];

        wmma::fragment<wmma::accumulator,16,16,16,float> acc;
        wmma::fill_fragment(acc, 0.f);

        auto issueA = [&](int kc, int stg) {
            bf16* dh = sA + (size_t)stg * ASTG;
            bf16* dl = dh + 64 * ALD;
#pragma unroll
            for (int i = 0; i < 4; i++) {
                int id = tid + 256 * i;          // 0..1023
                int half = id >> 9;
                int e = id & 511;
                int r = e >> 3, c = (e & 7) * 8;
                const bf16* src = (half ? hinL : hinH) + r * Hh + kc * 64 + c;
                cpasync16((half ? dl : dh) + r * ALD + c, src);
            }
            cpcommit();
        };

        issueA(0, 0); issueA(1, 1); issueA(2, 2);
        for (int kc = 0; kc < 16; kc++) {
            if      (kc <= 13) cpwait<2>();
            else if (kc == 14) cpwait<1>();
            else               cpwait<0>();
            __syncthreads();
            if (kc + 3 < 16) issueA(kc + 3, (kc + 3) & 3);
            bf16* dh = sA + (size_t)(kc & 3) * ASTG;
            bf16* dl = dh + 64 * ALD;
#pragma unroll
            for (int ks = 0; ks < 4; ks++) {
                wmma::fragment<wmma::matrix_a,16,16,16,bf16,wmma::row_major> ah, al;
                wmma::fragment<wmma::matrix_b,16,16,16,bf16,wmma::col_major> bhf, blf;
                wmma::load_matrix_sync(ah, dh + (wr*16)*ALD + ks*16, ALD);
                wmma::load_matrix_sync(al, dl + (wr*16)*ALD + ks*16, ALD);
                wmma::load_matrix_sync(bhf, sWh + (wc*16)*WLD + kc*64 + ks*16, WLD);
                wmma::load_matrix_sync(blf, sWl + (wc*16)*WLD + kc*64 + ks*16, WLD);
                wmma::mma_sync(acc, ah, bhf, acc);
                wmma::mma_sync(acc, ah, blf, acc);
                wmma::mma_sync(acc, al, bhf, acc);
            }
        }
        __syncthreads();
        wmma::store_matrix_sync(ghsm + (wr*16)*36 + wc*16, acc, 36, wmma::mem_row_major);
        __syncthreads();

#pragma unroll
        for (int e2 = 0; e2 < 2; e2++) {
            int b = bA + e2 * 32;
            float hprev = e2 ? hp1 : hp0;
            int   len   = e2 ? len1 : len0;
            float ghr = ghsm[b*36 + u]      + br;
            float ghz = ghsm[b*36 + 8 + u]  + bz;
            float ghn = ghsm[b*36 + 16 + u] + bn;
            const float* GIt = g_GI + ((size_t)t * Bb + b) * H3 + j0 + u;
            float gir = GIt[0]     + cr;
            float giz = GIt[Hh]    + cz;
            float gin = GIt[2*Hh]  + cn;
            float rg = 1.f / (1.f + expf(-(gir + ghr)));
            float zg = 1.f / (1.f + expf(-(giz + ghz)));
            float ng = tanhf(gin + rg * ghn);
            float keep = (t < len) ? 1.f : 0.f;
            float hn = (ng + zg * (hprev - ng)) * keep;
            if (e2) hp1 = hn; else hp0 = hn;

            int j = j0 + u;
            bf16 hhi = __float2bfloat16(hn);
            bf16 hlo = __float2bfloat16(hn - __bfloat162float(hhi));
            houtH[b*Hh + j] = hhi;
            houtL[b*Hh + j] = hlo;
            size_t hx = ((size_t)t * Bb + b) * Hh + j;
            g_hsh[hx] = hhi;
            g_hsl[hx] = hlo;
            hs[((size_t)t * Bb + b) * 2048 + j] = hn;
        }

        if (t < Ss - 1) {
            __syncthreads();
            if (tid == 0) {
                __threadfence();
                atomicAdd(&g_count, 1u);
                unsigned target = (unsigned)(t + 1) * SCAN_BLOCKS;
                while (*(volatile unsigned*)&g_count < target)
                    __nanosleep(32);
                __threadfence();
            }
            __syncthreads();
        }
    }
}

// ---------------- small kernels ----------------
__global__ void init_h_kernel(const float* __restrict__ h_init) {
    int idx = blockIdx.x * blockDim.x + threadIdx.x;   // 65536
    float v = h_init[idx & (Hh - 1)];
    bf16 hi = __float2bfloat16(v);
    g_ch_h[0][idx] = hi;
    g_ch_l[0][idx] = __float2bfloat16(v - __bfloat162float(hi));
    if (idx == 0) g_count = 0;
}

// masked softmax over l; attn fp32 [S][L][B] in place; split out [b][s][l]
__global__ void softmax_kernel(float* __restrict__ attn,
                               const int* __restrict__ post_length,
                               bf16* __restrict__ ah, bf16* __restrict__ al)
{
    extern __shared__ float smf[];                     // [64][260]
    int s = blockIdx.x;
    float* base = attn + (size_t)s * Ll * Bb;
    for (int i = threadIdx.x; i < Ll * Bb; i += 256) {
        int l = i >> 6, b = i & 63;
        smf[b * 260 + l] = base[i];
    }
    __syncthreads();
    {
        int b = threadIdx.x >> 2, q = threadIdx.x & 3;
        int plen = post_length[b];
        float* row = smf + b * 260;
        float m = -INFINITY;
        for (int l = q; l < plen; l += 4) m = fmaxf(m, row[l]);
        m = fmaxf(m, __shfl_xor_sync(0xffffffff, m, 1));
        m = fmaxf(m, __shfl_xor_sync(0xffffffff, m, 2));
        float sum = 0.f;
        for (int l = q; l < plen; l += 4) {
            float e = expf(row[l] - m);
            row[l] = e;
            sum += e;
        }
        sum += __shfl_xor_sync(0xffffffff, sum, 1);
        sum += __shfl_xor_sync(0xffffffff, sum, 2);
        float inv = 1.f / sum;
        for (int l = q; l < plen; l += 4) row[l] *= inv;
        for (int l = plen + q; l < Ll; l += 4) row[l] = 0.f;
    }
    __syncthreads();
    for (int i = threadIdx.x; i < Ll * Bb; i += 256) {
        int l = i >> 6, b = i & 63;
        base[i] = smf[b * 260 + l];
    }
    for (int i = threadIdx.x; i < Ll * Bb; i += 256) {
        int b = i >> 8, l = i & 255;
        float v = smf[b * 260 + l];
        bf16 hi = __float2bfloat16(v);
        size_t off = (size_t)b * (Ss * Ll) + (size_t)s * Ll + l;
        ah[off] = hi;
        al[off] = __float2bfloat16(v - __bfloat162float(hi));
    }
}

__global__ void copy_hlast_kernel(const float* __restrict__ hs, float* __restrict__ out) {
    int idx = blockIdx.x * blockDim.x + threadIdx.x;   // 65536
    int b = idx >> 10, j = idx & 1023;
    out[idx] = hs[((size_t)255 * Bb + b) * 2048 + j];
}

// ---------------- launcher ----------------
extern "C" void kernel_launch(void* const* d_in, const int* in_sizes, int n_in,
                              void* d_out, int out_size)
{
    (void)in_sizes; (void)n_in; (void)out_size;
    const float* incoming = (const float*)d_in[0];
    const float* post     = (const float*)d_in[1];
    const float* h_init   = (const float*)d_in[2];
    const float* W_ih     = (const float*)d_in[3];
    const float* W_hh     = (const float*)d_in[4];
    const float* b_ih     = (const float*)d_in[5];
    const float* b_hh     = (const float*)d_in[6];
    const float* Wq       = (const float*)d_in[7];
    const float* bq       = (const float*)d_in[8];
    const int*   length   = (const int*)d_in[9];
    const int*   plen     = (const int*)d_in[10];

    float* out    = (float*)d_out;
    float* h_last = out;
    float* hs     = out + (size_t)Bb * Hh;
    float* attn   = hs + (size_t)Ss * Bb * 2048;

    float *GI;
    bf16 *inch, *incl, *WihH, *WihL, *WhhH, *WhhL, *WqH, *WqL;
    bf16 *Qh, *Ql, *ph, *pl, *ah, *al, *hsH, *hsL;
    cudaGetSymbolAddress((void**)&GI,   g_GI);
    cudaGetSymbolAddress((void**)&inch, g_inch);
    cudaGetSymbolAddress((void**)&incl, g_incl);
    cudaGetSymbolAddress((void**)&WihH, g_Wih_h);
    cudaGetSymbolAddress((void**)&WihL, g_Wih_l);
    cudaGetSymbolAddress((void**)&WhhH, g_Whh_h);
    cudaGetSymbolAddress((void**)&WhhL, g_Whh_l);
    cudaGetSymbolAddress((void**)&WqH,  g_Wq_h);
    cudaGetSymbolAddress((void**)&WqL,  g_Wq_l);
    cudaGetSymbolAddress((void**)&Qh,   g_Qh);
    cudaGetSymbolAddress((void**)&Ql,   g_Ql);
    cudaGetSymbolAddress((void**)&ph,   g_ph);
    cudaGetSymbolAddress((void**)&pl,   g_pl);
    cudaGetSymbolAddress((void**)&ah,   g_ah);
    cudaGetSymbolAddress((void**)&al,   g_al);
    cudaGetSymbolAddress((void**)&hsH,  g_hsh);
    cudaGetSymbolAddress((void**)&hsL,  g_hsl);

    const int GEMM_SMEM = 2 * 4 * 128 * 40 * (int)sizeof(bf16);         // 81920
    const int NN_SMEM   = 2 * (2*128*40 + 2*32*136) * (int)sizeof(bf16); // 75776
    const int SCAN_SMEM = (2*32*1032 + 4*2*64*72) * (int)sizeof(bf16);  // 205824
    const int SFT_SMEM  = 64 * 260 * (int)sizeof(float);                // 66560
    cudaFuncSetAttribute(wmma_split_nt,
                         cudaFuncAttributeMaxDynamicSharedMemorySize, GEMM_SMEM);
    cudaFuncSetAttribute(wmma_split_nn,
                         cudaFuncAttributeMaxDynamicSharedMemorySize, NN_SMEM);
    cudaFuncSetAttribute(gru_scan,
                         cudaFuncAttributeMaxDynamicSharedMemorySize, SCAN_SMEM);
    cudaFuncSetAttribute(softmax_kernel,
                         cudaFuncAttributeMaxDynamicSharedMemorySize, SFT_SMEM);

    // 1-5) init + splits (order chosen so launch #6 = GI for ncu -s 5 -c 1)
    init_h_kernel<<<256, 256>>>(h_init);
    split_kernel<<<(Ss*Bb*Ii + 255)/256, 256>>>(incoming, inch, incl, Ss*Bb*Ii);
    split_kernel<<<(H3*Ii + 255)/256, 256>>>(W_ih, WihH, WihL, H3*Ii);
    split_kernel<<<(H3*Hh + 255)/256, 256>>>(W_hh, WhhH, WhhL, H3*Hh);
    split_kernel<<<(Pp*Hh + 255)/256, 256>>>(Wq, WqH, WqL, Pp*Hh);

    // 6) GI = incoming @ W_ih^T   (captured by ncu)
    wmma_split_nt<<<dim3(Ss*Bb/128, H3/128, 1), 256, GEMM_SMEM>>>(
        inch, incl, Ii, 0,  WihH, WihL, Ii, 0,
        GI, H3, 1, 0,  nullptr, nullptr, nullptr,  Ii);

    // 7) split post
    split_kernel<<<(Ll*Bb*Pp + 255)/256, 256>>>(post, ph, pl, Ll*Bb*Pp);

    // 8) persistent scan (one launch, 256 steps)
    gru_scan<<<SCAN_BLOCKS, 256, SCAN_SMEM>>>(b_ih, b_hh, length, h_init, hs);

    // 9) Q = h_hist @ Wq^T + bq  -> split directly (fused epilogue)
    wmma_split_nt<<<dim3(Ss*Bb/128, Pp/128, 1), 256, GEMM_SMEM>>>(
        hsH, hsL, Hh, 0,  WqH, WqL, Hh, 0,
        nullptr, Pp, 1, 0,  bq, Qh, Ql,  Hh);

    // 10) scores[s,l,b] = Q_b[s,:] . post_b[l,:]
    wmma_split_nt<<<dim3(Ss/128, Ll/128, Bb), 256, GEMM_SMEM>>>(
        Qh, Ql, (long)Bb*Pp, Pp,  ph, pl, (long)Bb*Pp, Pp,
        attn, (long)Ll*Bb, Bb, 1,  nullptr, nullptr, nullptr,  Pp);

    // 11) masked softmax + attn split
    softmax_kernel<<<Ss, 256, SFT_SMEM>>>(attn, plen, ah, al);

    // 12) context = attn @ post  -> hs[:, :, H:2H]  (tensor cores)
    wmma_split_nn<<<dim3(Ss/128, Pp/128, Bb), 256, NN_SMEM>>>(
        ah, al, Ll, (long)Ss*Ll,
        ph, pl, (long)Bb*Pp, Pp,
        hs + Hh, (long)Bb*2048, 2048,  Ll);

    // 13) h_last
    copy_hlast_kernel<<<256, 256>>>(hs, h_last);
}